// round 14
// baseline (speedup 1.0000x reference)
#include <cuda_runtime.h>
#include <math.h>

#define BB 32
#define NN 384
#define RR 16
#define THREADS 384
#define ROWS_PER_BLOCK 32
#define ROW_CHUNKS (NN / ROWS_PER_BLOCK)          // 12
#define ORDER_BLOCKS (BB * ROW_CHUNKS)            // 384
#define REL_BLOCKS ((BB * NN) / THREADS)          // 32
#define GRID (ORDER_BLOCKS + REL_BLOCKS)          // 416
#define NWARPS (THREADS / 32)                     // 12

// Scratch (no alloc allowed) — per-block partials + completion counter.
__device__ double g_osum[ORDER_BLOCKS];
__device__ double g_ocnt[ORDER_BLOCKS];
__device__ double g_rsum[REL_BLOCKS];
__device__ double g_rcnt[REL_BLOCKS];
__device__ unsigned int g_done = 0;

__global__ __launch_bounds__(THREADS)
void fused_kernel(const float* __restrict__ logits,
                  const float* __restrict__ rl,
                  const int* __restrict__ ro,
                  const int* __restrict__ parent,
                  const int* __restrict__ relation,
                  const int* __restrict__ mask,
                  float* __restrict__ out, int out_size) {
    __shared__ int ro_s[NN];
    __shared__ int m_s[NN];
    __shared__ double ws[NWARPS], wc[NWARPS], ws2[NWARPS], wc2[NWARPS];
    __shared__ bool is_last;

    const int t    = threadIdx.x;
    const int warp = t >> 5;
    const int lane = t & 31;

    double blk_s = 0.0, blk_c = 0.0;

    if (blockIdx.x < ORDER_BLOCKS) {
        // ------------- order BCE: EXACT R2 structure (1.44 TB/s) -------------
        const int b  = blockIdx.x / ROW_CHUNKS;
        const int i0 = (blockIdx.x % ROW_CHUNKS) * ROWS_PER_BLOCK;
        const int j  = t;

        ro_s[j] = ro[b * NN + j];
        m_s[j]  = mask[b * NN + j];
        __syncthreads();

        const int  ro_j = ro_s[j];
        const bool m_j  = (m_s[j] != 0);

        const float* base = logits + ((size_t)b * NN + i0) * NN + j;

        float fsum = 0.0f;
        int   cnt  = 0;

        #pragma unroll 8
        for (int ii = 0; ii < ROWS_PER_BLOCK; ii++) {
            const int i = i0 + ii;
            const float x = __ldg(base + (size_t)ii * NN);
            const bool valid = m_j && (m_s[i] != 0) && (i != j);
            const float tt = (ro_s[i] < ro_j) ? 1.0f : 0.0f;
            // stable softplus: max(x,0) + log(1 + exp(-|x|))
            const float ax = fabsf(x);
            const float sp = fmaxf(x, 0.0f) + __logf(1.0f + __expf(-ax));
            const float bce = sp - x * tt;
            if (valid) { fsum += bce; cnt++; }
        }

        blk_s = (double)fsum;
        blk_c = (double)cnt;
    } else {
        // ---------------- relation CE part (R2 structure) ----------------
        const int idx = (blockIdx.x - ORDER_BLOCKS) * THREADS + t;
        const int b = idx / NN;
        const int i = idx - b * NN;
        const int p = parent[idx];
        int       r = relation[idx];
        float ce = 0.0f;
        int   v  = 0;
        if (mask[idx] != 0 && p >= 0 && p < NN && r >= 0) {
            r = min(r, RR - 1);
            const float4* row =
                (const float4*)(rl + (((size_t)b * NN + p) * NN + i) * RR);
            float4 v0 = __ldg(row + 0);
            float4 v1 = __ldg(row + 1);
            float4 v2 = __ldg(row + 2);
            float4 v3 = __ldg(row + 3);
            float vals[RR] = {v0.x,v0.y,v0.z,v0.w, v1.x,v1.y,v1.z,v1.w,
                              v2.x,v2.y,v2.z,v2.w, v3.x,v3.y,v3.z,v3.w};
            float m = vals[0];
            #pragma unroll
            for (int k = 1; k < RR; k++) m = fmaxf(m, vals[k]);
            float ssum = 0.0f;
            #pragma unroll
            for (int k = 0; k < RR; k++) ssum += __expf(vals[k] - m);
            ce = m + __logf(ssum) - vals[r];
            v = 1;
        }
        blk_s = (double)ce;
        blk_c = (double)v;
        __syncthreads();   // keep barrier count symmetric with order path
    }

    // ---------------- block reduction (both paths) ----------------
    #pragma unroll
    for (int off = 16; off > 0; off >>= 1) {
        blk_s += __shfl_down_sync(0xffffffffu, blk_s, off);
        blk_c += __shfl_down_sync(0xffffffffu, blk_c, off);
    }
    if (lane == 0) { ws[warp] = blk_s; wc[warp] = blk_c; }
    __syncthreads();
    if (t == 0) {
        double S = 0.0, C = 0.0;
        #pragma unroll
        for (int w = 0; w < NWARPS; w++) { S += ws[w]; C += wc[w]; }
        if (blockIdx.x < ORDER_BLOCKS) {
            g_osum[blockIdx.x] = S;
            g_ocnt[blockIdx.x] = C;
        } else {
            g_rsum[blockIdx.x - ORDER_BLOCKS] = S;
            g_rcnt[blockIdx.x - ORDER_BLOCKS] = C;
        }
    }

    // ---------------- last-block finalize ----------------
    __threadfence();
    if (t == 0) {
        is_last = (atomicAdd(&g_done, 1u) == (unsigned)(GRID - 1));
    }
    __syncthreads();
    if (!is_last) return;

    double os = 0.0, oc = 0.0, rs = 0.0, rc = 0.0;
    for (int k = t; k < ORDER_BLOCKS; k += THREADS) {
        os += __ldcg(&g_osum[k]);
        oc += __ldcg(&g_ocnt[k]);
    }
    if (t < REL_BLOCKS) {
        rs = __ldcg(&g_rsum[t]);
        rc = __ldcg(&g_rcnt[t]);
    }
    #pragma unroll
    for (int off = 16; off > 0; off >>= 1) {
        os += __shfl_down_sync(0xffffffffu, os, off);
        oc += __shfl_down_sync(0xffffffffu, oc, off);
        rs += __shfl_down_sync(0xffffffffu, rs, off);
        rc += __shfl_down_sync(0xffffffffu, rc, off);
    }
    if (lane == 0) { ws[warp] = os; wc[warp] = oc; ws2[warp] = rs; wc2[warp] = rc; }
    __syncthreads();
    if (t == 0) {
        double OS = 0.0, OC = 0.0, RS = 0.0, RC = 0.0;
        #pragma unroll
        for (int w = 0; w < NWARPS; w++) {
            OS += ws[w]; OC += wc[w]; RS += ws2[w]; RC += wc2[w];
        }
        const double order_loss = OS / fmax(OC, 1.0);
        const double rel_loss   = RS / fmax(RC, 1.0);
        const double total = order_loss + 0.5 * rel_loss;
        out[0] = (float)total;
        if (out_size > 1) out[1] = (float)order_loss;
        if (out_size > 2) out[2] = (float)rel_loss;
        g_done = 0;   // reset for next graph replay
    }
}

extern "C" void kernel_launch(void* const* d_in, const int* in_sizes, int n_in,
                              void* d_out, int out_size) {
    const float* order_logits    = (const float*)d_in[0];
    const float* relation_logits = (const float*)d_in[1];
    const int*   reading_orders  = (const int*)d_in[2];
    const int*   parent_ids      = (const int*)d_in[3];
    const int*   relations       = (const int*)d_in[4];
    const int*   region_mask     = (const int*)d_in[5];
    float* out = (float*)d_out;

    fused_kernel<<<GRID, THREADS>>>(order_logits, relation_logits,
                                    reading_orders, parent_ids, relations,
                                    region_mask, out, out_size);
}

// round 15
// speedup vs baseline: 1.0887x; 1.0887x over previous
#include <cuda_runtime.h>
#include <math.h>
#include <stdint.h>

#define BB 32
#define NN 384
#define RR 16
#define THREADS 384
#define TILE_R 8
#define NTILES 12                                  // tiles per order block
#define ROWS_PER_BLOCK (TILE_R * NTILES)           // 96
#define ORDER_BLOCKS (BB * (NN / ROWS_PER_BLOCK))  // 128
#define GRID ORDER_BLOCKS                          // 128 (rel embedded)
#define NWARPS (THREADS / 32)                      // 12
#define HUGE_RO 0x3fffffff
#define LN2F 0.69314718055994531f

__device__ double g_osum[ORDER_BLOCKS];
__device__ double g_ocnt[ORDER_BLOCKS];
__device__ double g_rsum[ORDER_BLOCKS];
__device__ double g_rcnt[ORDER_BLOCKS];
__device__ unsigned int g_done = 0;

__device__ __forceinline__ uint32_t smem_u32(const void* p) {
    return (uint32_t)__cvta_generic_to_shared(p);
}

// Each thread copies 2x16B of the 12288-byte tile (384 threads * 32B).
__device__ __forceinline__ void prefetch_tile(const float* __restrict__ src,
                                              float* dst, int t) {
    const uint32_t d = smem_u32(dst) + t * 16;
    const char* s = (const char*)src + t * 16;
    asm volatile("cp.async.cg.shared.global [%0], [%1], 16;" :: "r"(d), "l"(s) : "memory");
    asm volatile("cp.async.cg.shared.global [%0], [%1], 16;" :: "r"(d + 6144), "l"(s + 6144) : "memory");
}
#define CP_COMMIT()  asm volatile("cp.async.commit_group;" ::: "memory")
#define CP_WAIT1()   asm volatile("cp.async.wait_group 1;" ::: "memory")

__global__ __launch_bounds__(THREADS)
void fused_kernel(const float* __restrict__ logits,
                  const float* __restrict__ rl,
                  const int* __restrict__ ro,
                  const int* __restrict__ parent,
                  const int* __restrict__ relation,
                  const int* __restrict__ mask,
                  float* __restrict__ out, int out_size) {
    __shared__ __align__(16) float buf[2][TILE_R * NN];   // 2 x 12 KB
    __shared__ __align__(8) int2 s2[NN];                  // {ro-or-HUGE, mask float}
    __shared__ double ws[NWARPS], wc[NWARPS], ws2[NWARPS], wc2[NWARPS];
    __shared__ bool is_last;

    const int t    = threadIdx.x;
    const int warp = t >> 5;
    const int lane = t & 31;

    const int b    = blockIdx.x >> 2;
    const int row0 = (blockIdx.x & 3) * ROWS_PER_BLOCK;
    const int j    = t;

    // ---- embedded relation item (one per thread for t < 96) ----
    // Issue its loads FIRST: the dependent-gather latency hides under the
    // whole order pipeline below.
    float4 rv0, rv1, rv2, rv3;
    bool   rvalid = false;
    int    rr = 0;
    if (t < 96) {
        const int ridx = blockIdx.x * 96 + t;
        const int p  = parent[ridx];
        const int r  = relation[ridx];
        const int mk = mask[ridx];
        rvalid = (mk != 0) && (p >= 0) && (p < NN) && (r >= 0);
        const int ps = rvalid ? p : 0;
        rr = rvalid ? min(r, RR - 1) : 0;
        const int b2 = ridx / NN;
        const int i2 = ridx - b2 * NN;
        const float4* row =
            (const float4*)(rl + (((size_t)b2 * NN + ps) * NN + i2) * RR);
        rv0 = __ldg(row + 0);
        rv1 = __ldg(row + 1);
        rv2 = __ldg(row + 2);
        rv3 = __ldg(row + 3);
    }

    // ---- order block prologue (R11 structure) ----
    const int m_me  = mask[b * NN + j];
    const int ro_me = ro[b * NN + j];
    const float xdiag = __ldg(logits + (((size_t)b * NN + j) * NN + j));
    int2 pack;
    pack.x = m_me ? ro_me : HUGE_RO;
    pack.y = __float_as_int(m_me ? 1.0f : 0.0f);
    s2[j] = pack;

    const float* tbase = logits + ((size_t)b * NN + row0) * NN;
    prefetch_tile(tbase,               buf[0], t); CP_COMMIT();   // tile 0
    prefetch_tile(tbase + TILE_R * NN, buf[1], t); CP_COMMIT();   // tile 1

    // Barrier publishes s2 AND counts valid rows in this block's range.
    const int nv = __syncthreads_count(
        (j >= row0 && j < row0 + ROWS_PER_BLOCK) ? m_me : 0);

    const int  sj = pack.x;
    const bool pj = (sj < HUGE_RO);

    float ysum = 0.0f;   // Σ mif·max(y,0)
    float lsum = 0.0f;   // Σ log2(Π(1 + mif·e))

    for (int tt = 0; tt < NTILES; tt++) {
        CP_WAIT1();
        __syncthreads();                       // tile tt resident in buf[tt&1]
        const float* bp = buf[tt & 1];
        const int i0 = row0 + tt * TILE_R;

        float u[TILE_R];
        #pragma unroll
        for (int q = 0; q < TILE_R; q++) {
            const float x   = bp[q * NN + j];
            const int2  v2  = s2[i0 + q];
            const float mif = __int_as_float(v2.y);
            const float y   = (v2.x < sj) ? -x : x;
            ysum = fmaf(mif, fmaxf(y, 0.0f), ysum);
            const float e   = __expf(-fabsf(x));
            u[q] = fmaf(e, mif, 1.0f);
        }
        const float p = ((u[0] * u[1]) * (u[2] * u[3])) *
                        ((u[4] * u[5]) * (u[6] * u[7]));
        lsum += __log2f(p);                    // one LG2 per 8 elems

        __syncthreads();                       // everyone done reading buf[tt&1]
        if (tt + 2 < NTILES)
            prefetch_tile(tbase + (size_t)(tt + 2) * TILE_R * NN,
                          buf[tt & 1], t);
        CP_COMMIT();                           // empty groups keep count exact
    }

    double blk_s = 0.0, blk_c = 0.0;
    {
        int cnt = 0;
        if (pj) {
            cnt = nv;
            if (j >= row0 && j < row0 + ROWS_PER_BLOCK) {   // diagonal correction
                ysum -= fmaxf(xdiag, 0.0f);
                lsum -= __log2f(1.0f + __expf(-fabsf(xdiag)));
                cnt--;
            }
            blk_s = (double)(ysum + LN2F * lsum);
        }
        blk_c = (double)cnt;
    }

    // ---- embedded relation CE compute (data long since arrived) ----
    double rel_s = 0.0, rel_c = 0.0;
    if (rvalid) {
        float vals[RR] = {rv0.x,rv0.y,rv0.z,rv0.w, rv1.x,rv1.y,rv1.z,rv1.w,
                          rv2.x,rv2.y,rv2.z,rv2.w, rv3.x,rv3.y,rv3.z,rv3.w};
        float m = vals[0];
        #pragma unroll
        for (int k = 1; k < RR; k++) m = fmaxf(m, vals[k]);
        float ssum = 0.0f;
        #pragma unroll
        for (int k = 0; k < RR; k++) ssum += __expf(vals[k] - m);
        rel_s = (double)(m + __logf(ssum) - vals[rr]);
        rel_c = 1.0;
    }

    // ---------------- block reduction (order + rel together) ----------------
    #pragma unroll
    for (int off = 16; off > 0; off >>= 1) {
        blk_s += __shfl_down_sync(0xffffffffu, blk_s, off);
        blk_c += __shfl_down_sync(0xffffffffu, blk_c, off);
        rel_s += __shfl_down_sync(0xffffffffu, rel_s, off);
        rel_c += __shfl_down_sync(0xffffffffu, rel_c, off);
    }
    if (lane == 0) { ws[warp] = blk_s; wc[warp] = blk_c;
                     ws2[warp] = rel_s; wc2[warp] = rel_c; }
    __syncthreads();
    if (t == 0) {
        double S = 0.0, C = 0.0, RS = 0.0, RC = 0.0;
        #pragma unroll
        for (int w = 0; w < NWARPS; w++) {
            S += ws[w]; C += wc[w]; RS += ws2[w]; RC += wc2[w];
        }
        g_osum[blockIdx.x] = S;
        g_ocnt[blockIdx.x] = C;
        g_rsum[blockIdx.x] = RS;
        g_rcnt[blockIdx.x] = RC;
    }

    // ---------------- last-block finalize ----------------
    __threadfence();
    if (t == 0) {
        is_last = (atomicAdd(&g_done, 1u) == (unsigned)(GRID - 1));
    }
    __syncthreads();
    if (!is_last) return;

    double os = 0.0, oc = 0.0, rs = 0.0, rc = 0.0;
    if (t < ORDER_BLOCKS) {
        os = __ldcg(&g_osum[t]);
        oc = __ldcg(&g_ocnt[t]);
        rs = __ldcg(&g_rsum[t]);
        rc = __ldcg(&g_rcnt[t]);
    }
    #pragma unroll
    for (int off = 16; off > 0; off >>= 1) {
        os += __shfl_down_sync(0xffffffffu, os, off);
        oc += __shfl_down_sync(0xffffffffu, oc, off);
        rs += __shfl_down_sync(0xffffffffu, rs, off);
        rc += __shfl_down_sync(0xffffffffu, rc, off);
    }
    if (lane == 0) { ws[warp] = os; wc[warp] = oc; ws2[warp] = rs; wc2[warp] = rc; }
    __syncthreads();
    if (t == 0) {
        double OS = 0.0, OC = 0.0, RS = 0.0, RC = 0.0;
        #pragma unroll
        for (int w = 0; w < NWARPS; w++) {
            OS += ws[w]; OC += wc[w]; RS += ws2[w]; RC += wc2[w];
        }
        const double order_loss = OS / fmax(OC, 1.0);
        const double rel_loss   = RS / fmax(RC, 1.0);
        const double total = order_loss + 0.5 * rel_loss;
        out[0] = (float)total;
        if (out_size > 1) out[1] = (float)order_loss;
        if (out_size > 2) out[2] = (float)rel_loss;
        g_done = 0;   // reset for next graph replay
    }
}

extern "C" void kernel_launch(void* const* d_in, const int* in_sizes, int n_in,
                              void* d_out, int out_size) {
    const float* order_logits    = (const float*)d_in[0];
    const float* relation_logits = (const float*)d_in[1];
    const int*   reading_orders  = (const int*)d_in[2];
    const int*   parent_ids      = (const int*)d_in[3];
    const int*   relations       = (const int*)d_in[4];
    const int*   region_mask     = (const int*)d_in[5];
    float* out = (float*)d_out;

    fused_kernel<<<GRID, THREADS>>>(order_logits, relation_logits,
                                    reading_orders, parent_ids, relations,
                                    region_mask, out, out_size);
}

// round 16
// speedup vs baseline: 1.2557x; 1.1534x over previous
#include <cuda_runtime.h>
#include <math.h>
#include <stdint.h>

#define BB 32
#define NN 384
#define RR 16
#define THREADS 384
#define TILE_R 8
#define NTILES 12                                  // tiles per order block
#define ROWS_PER_BLOCK (TILE_R * NTILES)           // 96
#define ORDER_BLOCKS (BB * (NN / ROWS_PER_BLOCK))  // 128
#define REL_BLOCKS 8
#define REL_ITEMS_PER_T 4                          // 8*384*4 = 12288
#define GRID (ORDER_BLOCKS + REL_BLOCKS)           // 136
#define NWARPS (THREADS / 32)                      // 12
#define HUGE_RO 0x3fffffff
#define LN2F 0.69314718055994531f

__device__ double g_osum[ORDER_BLOCKS];
__device__ double g_ocnt[ORDER_BLOCKS];
__device__ double g_rsum[REL_BLOCKS];
__device__ double g_rcnt[REL_BLOCKS];
__device__ unsigned int g_done = 0;

__device__ __forceinline__ uint32_t smem_u32(const void* p) {
    return (uint32_t)__cvta_generic_to_shared(p);
}

// Each thread copies 2x16B of the 12288-byte tile (384 threads * 32B).
__device__ __forceinline__ void prefetch_tile(const float* __restrict__ src,
                                              float* dst, int t) {
    const uint32_t d = smem_u32(dst) + t * 16;
    const char* s = (const char*)src + t * 16;
    asm volatile("cp.async.cg.shared.global [%0], [%1], 16;" :: "r"(d), "l"(s) : "memory");
    asm volatile("cp.async.cg.shared.global [%0], [%1], 16;" :: "r"(d + 6144), "l"(s + 6144) : "memory");
}
#define CP_COMMIT()  asm volatile("cp.async.commit_group;" ::: "memory")
#define CP_WAIT1()   asm volatile("cp.async.wait_group 1;" ::: "memory")

__global__ __launch_bounds__(THREADS)
void fused_kernel(const float* __restrict__ logits,
                  const float* __restrict__ rl,
                  const int* __restrict__ ro,
                  const int* __restrict__ parent,
                  const int* __restrict__ relation,
                  const int* __restrict__ mask,
                  float* __restrict__ out, int out_size) {
    __shared__ __align__(16) float buf[2][TILE_R * NN];   // 2 x 12 KB
    __shared__ __align__(8) int2 s2[NN];                  // {ro-or-HUGE, mask float}
    __shared__ double ws[NWARPS], wc[NWARPS], ws2[NWARPS], wc2[NWARPS];
    __shared__ bool is_last;

    const int t    = threadIdx.x;
    const int warp = t >> 5;
    const int lane = t & 31;

    double blk_s = 0.0, blk_c = 0.0;

    if (blockIdx.x < ORDER_BLOCKS) {
        // ---------------- order BCE: pipelined over 12 tiles of 8 rows ------
        const int b    = blockIdx.x >> 2;
        const int row0 = (blockIdx.x & 3) * ROWS_PER_BLOCK;
        const int j    = t;

        const int m_me  = mask[b * NN + j];
        const int ro_me = ro[b * NN + j];
        // Diagonal logit prefetched NOW — its DRAM latency overlaps the
        // whole 12-tile pipeline instead of sitting exposed on the tail.
        const float xdiag = __ldg(logits + (((size_t)b * NN + j) * NN + j));
        int2 pack;
        pack.x = m_me ? ro_me : HUGE_RO;
        pack.y = __float_as_int(m_me ? 1.0f : 0.0f);
        s2[j] = pack;

        const float* tbase = logits + ((size_t)b * NN + row0) * NN;
        prefetch_tile(tbase,               buf[0], t); CP_COMMIT();   // tile 0
        prefetch_tile(tbase + TILE_R * NN, buf[1], t); CP_COMMIT();   // tile 1

        // Barrier publishes s2 AND counts valid rows in this block's range.
        const int nv96 = __syncthreads_count(
            (j >= row0 && j < row0 + ROWS_PER_BLOCK) ? m_me : 0);

        const int  sj = pack.x;
        const bool pj = (sj < HUGE_RO);

        float ysum = 0.0f;   // Σ mif·max(y,0)
        float lsum = 0.0f;   // Σ log2(Π(1 + mif·e))

        for (int tt = 0; tt < NTILES; tt++) {
            CP_WAIT1();
            __syncthreads();                       // tile tt resident in buf[tt&1]
            const float* bp = buf[tt & 1];
            const int i0 = row0 + tt * TILE_R;

            float u[TILE_R];
            #pragma unroll
            for (int q = 0; q < TILE_R; q++) {
                const float x   = bp[q * NN + j];
                const int2  v2  = s2[i0 + q];
                const float mif = __int_as_float(v2.y);
                const float y   = (v2.x < sj) ? -x : x;
                ysum = fmaf(mif, fmaxf(y, 0.0f), ysum);
                const float e   = __expf(-fabsf(x));
                u[q] = fmaf(e, mif, 1.0f);
            }
            const float p = ((u[0] * u[1]) * (u[2] * u[3])) *
                            ((u[4] * u[5]) * (u[6] * u[7]));
            lsum += __log2f(p);                    // one LG2 per 8 elems

            __syncthreads();                       // everyone done reading buf[tt&1]
            if (tt + 2 < NTILES)
                prefetch_tile(tbase + (size_t)(tt + 2) * TILE_R * NN,
                              buf[tt & 1], t);
            CP_COMMIT();                           // empty groups keep count exact
        }

        int cnt = 0;
        if (pj) {
            cnt = nv96;
            if (j >= row0 && j < row0 + ROWS_PER_BLOCK) {   // diagonal correction
                ysum -= fmaxf(xdiag, 0.0f);
                lsum -= __log2f(1.0f + __expf(-fabsf(xdiag)));
                cnt--;
            }
            blk_s = (double)(ysum + LN2F * lsum);
        }
        blk_c = (double)cnt;
    } else {
        // ---------------- relation CE part ----------------
        const int rb = blockIdx.x - ORDER_BLOCKS;
        float ce_sum = 0.0f;
        int   v_sum  = 0;
        #pragma unroll
        for (int k = 0; k < REL_ITEMS_PER_T; k++) {
            const int idx = (rb * REL_ITEMS_PER_T + k) * THREADS + t;
            const int b = idx / NN;
            const int i = idx - b * NN;
            const int p = parent[idx];
            int       r = relation[idx];
            if (mask[idx] != 0 && p >= 0 && p < NN && r >= 0) {
                r = min(r, RR - 1);
                const float4* row =
                    (const float4*)(rl + (((size_t)b * NN + p) * NN + i) * RR);
                float4 v0 = __ldg(row + 0);
                float4 v1 = __ldg(row + 1);
                float4 v2 = __ldg(row + 2);
                float4 v3 = __ldg(row + 3);
                float vals[RR] = {v0.x,v0.y,v0.z,v0.w, v1.x,v1.y,v1.z,v1.w,
                                  v2.x,v2.y,v2.z,v2.w, v3.x,v3.y,v3.z,v3.w};
                float m = vals[0];
                #pragma unroll
                for (int q = 1; q < RR; q++) m = fmaxf(m, vals[q]);
                float ssum = 0.0f;
                #pragma unroll
                for (int q = 0; q < RR; q++) ssum += __expf(vals[q] - m);
                ce_sum += m + __logf(ssum) - vals[r];
                v_sum++;
            }
        }
        blk_s = (double)ce_sum;
        blk_c = (double)v_sum;
    }

    // ---------------- block reduction (both paths) ----------------
    #pragma unroll
    for (int off = 16; off > 0; off >>= 1) {
        blk_s += __shfl_down_sync(0xffffffffu, blk_s, off);
        blk_c += __shfl_down_sync(0xffffffffu, blk_c, off);
    }
    if (lane == 0) { ws[warp] = blk_s; wc[warp] = blk_c; }
    __syncthreads();
    if (t == 0) {
        double S = 0.0, C = 0.0;
        #pragma unroll
        for (int w = 0; w < NWARPS; w++) { S += ws[w]; C += wc[w]; }
        if (blockIdx.x < ORDER_BLOCKS) {
            g_osum[blockIdx.x] = S;
            g_ocnt[blockIdx.x] = C;
        } else {
            g_rsum[blockIdx.x - ORDER_BLOCKS] = S;
            g_rcnt[blockIdx.x - ORDER_BLOCKS] = C;
        }
    }

    // ---------------- last-block finalize ----------------
    __threadfence();
    if (t == 0) {
        is_last = (atomicAdd(&g_done, 1u) == (unsigned)(GRID - 1));
    }
    __syncthreads();
    if (!is_last) return;

    double os = 0.0, oc = 0.0, rs = 0.0, rc = 0.0;
    for (int k = t; k < ORDER_BLOCKS; k += THREADS) {
        os += __ldcg(&g_osum[k]);
        oc += __ldcg(&g_ocnt[k]);
    }
    if (t < REL_BLOCKS) {
        rs = __ldcg(&g_rsum[t]);
        rc = __ldcg(&g_rcnt[t]);
    }
    #pragma unroll
    for (int off = 16; off > 0; off >>= 1) {
        os += __shfl_down_sync(0xffffffffu, os, off);
        oc += __shfl_down_sync(0xffffffffu, oc, off);
        rs += __shfl_down_sync(0xffffffffu, rs, off);
        rc += __shfl_down_sync(0xffffffffu, rc, off);
    }
    if (lane == 0) { ws[warp] = os; wc[warp] = oc; ws2[warp] = rs; wc2[warp] = rc; }
    __syncthreads();
    if (t == 0) {
        double OS = 0.0, OC = 0.0, RS = 0.0, RC = 0.0;
        #pragma unroll
        for (int w = 0; w < NWARPS; w++) {
            OS += ws[w]; OC += wc[w]; RS += ws2[w]; RC += wc2[w];
        }
        const double order_loss = OS / fmax(OC, 1.0);
        const double rel_loss   = RS / fmax(RC, 1.0);
        const double total = order_loss + 0.5 * rel_loss;
        out[0] = (float)total;
        if (out_size > 1) out[1] = (float)order_loss;
        if (out_size > 2) out[2] = (float)rel_loss;
        g_done = 0;   // reset for next graph replay
    }
}

extern "C" void kernel_launch(void* const* d_in, const int* in_sizes, int n_in,
                              void* d_out, int out_size) {
    const float* order_logits    = (const float*)d_in[0];
    const float* relation_logits = (const float*)d_in[1];
    const int*   reading_orders  = (const int*)d_in[2];
    const int*   parent_ids      = (const int*)d_in[3];
    const int*   relations       = (const int*)d_in[4];
    const int*   region_mask     = (const int*)d_in[5];
    float* out = (float*)d_out;

    fused_kernel<<<GRID, THREADS>>>(order_logits, relation_logits,
                                    reading_orders, parent_ids, relations,
                                    region_mask, out, out_size);
}